// round 2
// baseline (speedup 1.0000x reference)
#include <cuda_runtime.h>
#include <math.h>

#define N 8192
#define NW (N/32)          // 256 mask words per j-row
#define S1 8               // j-splits, pass 1
#define S2 8               // j-splits, pass 2
#define TJ1 256            // j tile (pass 1, staged in smem)
#define JR1 (N/S1)         // 1024 j per block, pass 1
#define JR2 (N/S2)         // 1024 j per block, pass 2

// -------- scratch (static device globals; no allocation) --------
__device__ float g_y1[N*32];                   // 1 MB
__device__ float g_h[N*32];                    // 1 MB
__device__ float g_y2[N*8];                    // 256 KB
__device__ float g_invrow[N];                  // 32 KB
__device__ unsigned g_mask[(size_t)N*NW];      // 8 MB bitmask: word[j*NW + i/32], bit = lane
__device__ float g_part1[(size_t)S1*N*32];     // 8 MB
__device__ int   g_cnt[S1*N];                  // 256 KB
__device__ float g_part2[(size_t)S2*N*8];      // 2 MB

// ---------------- kernel 1: features + y1 = x@W1 + b1 ----------------
__global__ void feat_kernel(const float4* __restrict__ led, const float* __restrict__ B,
                            const float* __restrict__ emb, const float* __restrict__ W1,
                            const float* __restrict__ b1) {
    __shared__ float sB[48], semb[104], sW1[40*32], sb1[32];
    int t = threadIdx.x;
    if (t < 48)  sB[t]   = B[t];
    if (t < 104) semb[t] = emb[t];
    if (t < 32)  sb1[t]  = b1[t];
    for (int idx = t; idx < 40*32; idx += 256) sW1[idx] = W1[idx];
    __syncthreads();

    int i = blockIdx.x*256 + t;
    float4 p = led[i];
    float x[40];
    #pragma unroll
    for (int f = 0; f < 16; f++) {
        float pr = (p.x*sB[f] + p.y*sB[16+f] + p.z*sB[32+f]) * 6.283185307179586f;
        float sv, cv; sincosf(pr, &sv, &cv);
        x[f] = sv; x[16+f] = cv;
    }
    int fr = (int)p.w;
    #pragma unroll
    for (int e = 0; e < 8; e++) x[32+e] = semb[fr*8 + e];

    #pragma unroll 4
    for (int k = 0; k < 32; k++) {
        float acc = sb1[k];
        #pragma unroll
        for (int d = 0; d < 40; d++) acc = fmaf(x[d], sW1[d*32 + k], acc);
        g_y1[i*32 + k] = acc;
    }
}

// ---------------- kernel 2: pass 1 — masked sum of y1, build bitmask ----------------
__global__ void __launch_bounds__(256) pass1_kernel(const float4* __restrict__ led) {
    __shared__ __align__(16) float s_y[TJ1*32];   // 32 KB
    __shared__ float4 s_pos[TJ1];                 // 4 KB
    int t = threadIdx.x;
    int lane = t & 31;
    int i = blockIdx.x*256 + t;
    int s = blockIdx.y;
    int j0 = s*JR1;
    int iw = i >> 5;

    float4 pi = led[i];
    unsigned long long acc[16];
    #pragma unroll
    for (int k = 0; k < 16; k++) acc[k] = 0ull;
    int cnt = 0;

    for (int tile = 0; tile < JR1/TJ1; tile++) {
        int jt = j0 + tile*TJ1;
        __syncthreads();
        // stage y1 tile: TJ1*32 floats = 2048 float4, 8 per thread
        {
            const float4* src = (const float4*)&g_y1[(size_t)jt*32];
            float4* dst = (float4*)s_y;
            #pragma unroll
            for (int r = 0; r < 8; r++) dst[t + r*256] = src[t + r*256];
            s_pos[t] = led[jt + t];
        }
        __syncthreads();

        for (int jj = 0; jj < TJ1; jj++) {
            float4 pj = s_pos[jj];
            float dx = pi.x - pj.x, dy = pi.y - pj.y, dz = pi.z - pj.z;
            float d2 = fmaf(dx, dx, fmaf(dy, dy, dz*dz));
            bool pred = d2 < 6.25f;
            cnt += pred;
            unsigned w = __ballot_sync(0xffffffffu, pred);
            if (lane == 0) g_mask[(size_t)(jt + jj)*NW + iw] = w;

            unsigned mi = pred ? 0x3f800000u : 0u;
            unsigned long long m64;
            asm("mov.b64 %0, {%1, %1};" : "=l"(m64) : "r"(mi));

            const ulonglong2* yrow = (const ulonglong2*)&s_y[jj*32];
            #pragma unroll
            for (int q = 0; q < 8; q++) {
                ulonglong2 yv = yrow[q];
                asm("fma.rn.f32x2 %0, %1, %2, %0;" : "+l"(acc[2*q])   : "l"(m64), "l"(yv.x));
                asm("fma.rn.f32x2 %0, %1, %2, %0;" : "+l"(acc[2*q+1]) : "l"(m64), "l"(yv.y));
            }
        }
    }
    unsigned long long* dst = (unsigned long long*)&g_part1[((size_t)s*N + i)*32];
    #pragma unroll
    for (int k = 0; k < 16; k++) dst[k] = acc[k];
    g_cnt[s*N + i] = cnt;
}

// ---------------- kernel 3: reduce partials -> h = relu(sum * invrow) ----------------
__global__ void reduce1_kernel() {
    int idx = blockIdx.x*256 + threadIdx.x;   // N*32 threads
    int i = idx >> 5;
    float sum = 0.0f;
    #pragma unroll
    for (int s = 0; s < S1; s++) sum += g_part1[((size_t)s*N)*32 + idx];
    int c = 0;
    #pragma unroll
    for (int s = 0; s < S1; s++) c += g_cnt[s*N + i];
    float inv = 1.0f / ((float)c + 1e-6f);
    float h = sum * inv;
    g_h[idx] = h > 0.0f ? h : 0.0f;
    if ((idx & 31) == 0) g_invrow[i] = inv;
}

// ---------------- kernel 4: y2 = h@W2 + b2 ----------------
__global__ void y2_kernel(const float* __restrict__ W2, const float* __restrict__ b2) {
    __shared__ float sW2[32*8], sb2[8];
    int t = threadIdx.x;
    if (t < 256) sW2[t] = W2[t];
    if (t < 8)   sb2[t] = b2[t];
    __syncthreads();
    int i = blockIdx.x*256 + t;
    float h[32];
    #pragma unroll
    for (int d = 0; d < 32; d++) h[d] = g_h[i*32 + d];
    #pragma unroll
    for (int k = 0; k < 8; k++) {
        float a = sb2[k];
        #pragma unroll
        for (int d = 0; d < 32; d++) a = fmaf(h[d], sW2[d*8 + k], a);
        g_y2[i*8 + k] = a;
    }
}

// ---------------- kernel 5: pass 2 — masked sum of y2 (bitmask reuse) ----------------
__global__ void __launch_bounds__(256) pass2_kernel() {
    __shared__ __align__(16) float s_y[JR2*8];    // 32 KB
    int t = threadIdx.x, lane = t & 31;
    int i = blockIdx.x*256 + t;
    int s = blockIdx.y;
    int j0 = s*JR2;
    int iw = i >> 5;
    {
        const float4* src = (const float4*)&g_y2[(size_t)j0*8];
        float4* dst = (float4*)s_y;
        #pragma unroll
        for (int r = 0; r < 8; r++) dst[t + r*256] = src[t + r*256];
    }
    __syncthreads();

    unsigned long long acc[4] = {0ull, 0ull, 0ull, 0ull};
    for (int jj = 0; jj < JR2; jj++) {
        unsigned w = __ldg(&g_mask[(size_t)(j0 + jj)*NW + iw]);
        unsigned mi = ((w >> lane) & 1u) ? 0x3f800000u : 0u;
        unsigned long long m64;
        asm("mov.b64 %0, {%1, %1};" : "=l"(m64) : "r"(mi));
        const ulonglong2* yrow = (const ulonglong2*)&s_y[jj*8];
        ulonglong2 a = yrow[0], b = yrow[1];
        asm("fma.rn.f32x2 %0, %1, %2, %0;" : "+l"(acc[0]) : "l"(m64), "l"(a.x));
        asm("fma.rn.f32x2 %0, %1, %2, %0;" : "+l"(acc[1]) : "l"(m64), "l"(a.y));
        asm("fma.rn.f32x2 %0, %1, %2, %0;" : "+l"(acc[2]) : "l"(m64), "l"(b.x));
        asm("fma.rn.f32x2 %0, %1, %2, %0;" : "+l"(acc[3]) : "l"(m64), "l"(b.y));
    }
    unsigned long long* dst = (unsigned long long*)&g_part2[((size_t)s*N + i)*8];
    #pragma unroll
    for (int k = 0; k < 4; k++) dst[k] = acc[k];
}

// ---------------- kernel 6: reduce + relu -> out ----------------
__global__ void reduce2_kernel(float* __restrict__ out) {
    int idx = blockIdx.x*256 + threadIdx.x;   // N*8 threads
    int i = idx >> 3;
    float sum = 0.0f;
    #pragma unroll
    for (int s = 0; s < S2; s++) sum += g_part2[((size_t)s*N)*8 + idx];
    float v = sum * g_invrow[i];
    out[idx] = v > 0.0f ? v : 0.0f;
}

// ---------------- launch ----------------
extern "C" void kernel_launch(void* const* d_in, const int* in_sizes, int n_in,
                              void* d_out, int out_size) {
    const float4* led = (const float4*)d_in[0];   // [N,4] pos.xyz + freq
    const float*  B   = (const float*)d_in[1];    // [3,16]
    const float*  emb = (const float*)d_in[2];    // [13,8]
    const float*  W1  = (const float*)d_in[3];    // [40,32]
    const float*  b1  = (const float*)d_in[4];    // [32]
    const float*  W2  = (const float*)d_in[5];    // [32,8]
    const float*  b2  = (const float*)d_in[6];    // [8]
    float* out = (float*)d_out;                   // [N,8] fp32

    feat_kernel<<<32, 256>>>(led, B, emb, W1, b1);
    pass1_kernel<<<dim3(32, S1), 256>>>(led);
    reduce1_kernel<<<N*32/256, 256>>>();
    y2_kernel<<<32, 256>>>(W2, b2);
    pass2_kernel<<<dim3(32, S2), 256>>>();
    reduce2_kernel<<<N*8/256, 256>>>(out);
}